// round 1
// baseline (speedup 1.0000x reference)
#include <cuda_runtime.h>
#include <math.h>

#define N_WIN 800
#define RFLD  512
#define FCH   128
#define MGCSZ 60
#define NBLK  4
#define SQC   0.70710678118f

// ---------------- device scratch (no cudaMalloc allowed) ----------------
__device__ float g_prev[1312];                       // signal[:512] ++ new_x
__device__ float g_cond[N_WIN * MGCSZ];              // [800,60]
__device__ float g_ciAll[NBLK * 9 * 2 * N_WIN * FCH];// [blk,l,g,n,f]
__device__ float g_Wp[NBLK * 8 * 384 * 256];         // permuted layer weights
__device__ float g_bp[NBLK * 8 * 384];               // permuted biases
__device__ float g_hA[N_WIN * 256 * FCH];            // ping-pong activations
__device__ float g_hB[N_WIN * 256 * FCH];

__device__ __forceinline__ float sigm(float x) { return 1.f / (1.f + expf(-x)); }

// ---------------- init: prev <- signal, out[0:800] <- signal[512:] ------
__global__ void k_init(const float* __restrict__ sig, float* __restrict__ out) {
    int i = blockIdx.x * blockDim.x + threadIdx.x;
    if (i < 1312) g_prev[i] = sig[i];
    if (i < 800)  out[i] = sig[512 + i];
}

// ---------------- cond = tanh(mgc @ cond_w.T + b), reshaped [800,60] ----
__global__ void k_cond(const float* __restrict__ mgc, const float* __restrict__ cw,
                       const float* __restrict__ cb) {
    int id = blockIdx.x * 256 + threadIdx.x;
    if (id >= 4 * 12000) return;
    int t = id / 12000, w = id % 12000;
    const float* wr = cw + w * 60;
    const float* mg = mgc + t * 60;
    float s = cb[w];
#pragma unroll
    for (int k = 0; k < 60; k++) s += mg[k] * wr[k];
    g_cond[(t * 200 + w / 60) * 60 + (w % 60)] = tanhf(s);
}

// ---------------- all cond-linear projections: [72, 800, 128] -----------
__global__ void k_ciall(const float* __restrict__ clw, const float* __restrict__ clb) {
    __shared__ float cs[32][60];
    int wg = blockIdx.x;          // (blk*9 + l)*2 + g  in [0,72)
    int nt = blockIdx.y;          // n tile in [0,25)
    int f  = threadIdx.x;         // 0..127
    for (int i = f; i < 32 * 60; i += 128)
        cs[i / 60][i % 60] = g_cond[(nt * 32 + i / 60) * 60 + (i % 60)];
    __syncthreads();
    float wr[60];
    const float* wsrc = clw + (wg * 128 + f) * 60;
#pragma unroll
    for (int k = 0; k < 60; k++) wr[k] = wsrc[k];
    float b = clb[wg * 128 + f];
    for (int nn = 0; nn < 32; nn++) {
        float s = b;
#pragma unroll
        for (int k = 0; k < 60; k++) s += wr[k] * cs[nn][k];
        g_ciAll[(wg * 800 + nt * 32 + nn) * 128 + f] = s;
    }
}

// ---------------- weight permute: Wp[bl][f*3+t][kk*128+c] ----------------
__global__ void k_wprep(const float* __restrict__ wL, const float* __restrict__ bL) {
    int idx = blockIdx.x * 256 + threadIdx.x;
    const int total = NBLK * 8 * 384 * 256;
    if (idx < total) {
        int k  = idx & 255;
        int r  = (idx >> 8) % 384;
        int bl = idx / (384 * 256);        // blk*8 + (l-1)
        int f = r / 3, t = r % 3, kk = k >> 7, c = k & 127;
        g_Wp[idx] = wL[(((bl * 3 + t) * 128 + f) * 128 + c) * 2 + kk];
    }
    if (idx < NBLK * 8 * 384) {
        int r = idx % 384, bl = idx / 384;
        g_bp[idx] = bL[(bl * 3 + (r % 3)) * 128 + (r / 3)];
    }
}

// ---------------- layer 0 (Cin=1): out = g_hA [800,256,128] --------------
__global__ void k_layer0(const float* __restrict__ w0, const float* __restrict__ b0, int blk) {
    int gid = blockIdx.x * 256 + threadIdx.x;     // 800*256*128
    int m = gid >> 7, f = gid & 127;
    if (m >= 800 * 256) return;
    int n = m >> 8, j = m & 255;
    const float* ci = g_ciAll + (size_t)(blk * 9 * 2) * 102400;
    const float* cg = ci + 102400;
    float a = g_prev[n + 2 * j], b = g_prev[n + 2 * j + 1];
    float o0 = a * w0[f * 2]             + b * w0[f * 2 + 1]             + b0[f];
    float o1 = a * w0[(128 + f) * 2]     + b * w0[(128 + f) * 2 + 1]     + b0[128 + f];
    float o2 = a * w0[(256 + f) * 2]     + b * w0[(256 + f) * 2 + 1]     + b0[256 + f];
    float it = tanhf(o0 + ci[n * 128 + f]);
    float gt = sigm(o1 + cg[n * 128 + f]);
    g_hA[gid] = (it * gt + o2) * SQC;
}

// ------------ layers 1..8: GEMM [M,256]x[256,384] + fused gating ---------
// BM=128, BN=96 (32 f x 3 gates), BK=16; 256 threads, 8x6 accs each.
__global__ void __launch_bounds__(256, 2)
k_layer(int blk, int l, int M, int logL) {
    __shared__ float As[16][128];
    __shared__ float Bs[16][96];
    const float* __restrict__ A  = (l & 1) ? g_hA : g_hB;
    float* __restrict__ outp     = (l & 1) ? g_hB : g_hA;
    const float* __restrict__ Wp = g_Wp + (size_t)(blk * 8 + l - 1) * 384 * 256;
    const float* __restrict__ bp = g_bp + (blk * 8 + l - 1) * 384;
    const float* __restrict__ ci = g_ciAll + (size_t)((blk * 9 + l) * 2) * 102400;
    const float* __restrict__ cg = ci + 102400;

    int tid = threadIdx.x;
    int m0 = blockIdx.x * 128;
    int r0 = blockIdx.y * 96;
    int tx = tid & 15, ty = tid >> 4;

    float acc[8][6];
#pragma unroll
    for (int i = 0; i < 8; i++)
#pragma unroll
        for (int j = 0; j < 6; j++) acc[i][j] = 0.f;

    for (int k0 = 0; k0 < 256; k0 += 16) {
#pragma unroll
        for (int i = 0; i < 2; i++) {
            int idx4 = tid * 2 + i;           // 0..511
            int row = idx4 >> 2;              // 0..127
            int kq = (idx4 & 3) * 4;
            float4 v = make_float4(0.f, 0.f, 0.f, 0.f);
            int m = m0 + row;
            if (m < M) v = *reinterpret_cast<const float4*>(A + (size_t)m * 256 + k0 + kq);
            As[kq][row] = v.x; As[kq + 1][row] = v.y;
            As[kq + 2][row] = v.z; As[kq + 3][row] = v.w;
        }
#pragma unroll
        for (int i = 0; i < 6; i++) {
            int e = i * 256 + tid;            // 0..1535
            int r = e >> 4, k = e & 15;
            Bs[k][r] = Wp[(size_t)(r0 + r) * 256 + k0 + k];
        }
        __syncthreads();
#pragma unroll
        for (int k = 0; k < 16; k++) {
            float a[8], b[6];
#pragma unroll
            for (int i = 0; i < 8; i++) a[i] = As[k][ty * 8 + i];
#pragma unroll
            for (int j = 0; j < 6; j++) b[j] = Bs[k][tx * 6 + j];
#pragma unroll
            for (int i = 0; i < 8; i++)
#pragma unroll
                for (int j = 0; j < 6; j++) acc[i][j] += a[i] * b[j];
        }
        __syncthreads();
    }

    int f0 = (r0 + tx * 6) / 3;   // even f; covers f0, f0+1
#pragma unroll
    for (int i = 0; i < 8; i++) {
        int m = m0 + ty * 8 + i;
        if (m >= M) continue;
        int n = m >> logL;
#pragma unroll
        for (int p = 0; p < 2; p++) {
            int f = f0 + p;
            int rb = r0 + tx * 6 + p * 3;
            float o0 = acc[i][p * 3]     + bp[rb]     + ci[n * 128 + f];
            float o1 = acc[i][p * 3 + 1] + bp[rb + 1] + cg[n * 128 + f];
            float o2 = acc[i][p * 3 + 2] + bp[rb + 2];
            float it = tanhf(o0);
            float gt = sigm(o1);
            outp[(size_t)m * 128 + f] = (it * gt + o2) * SQC;
        }
    }
}

// ---------------- heads: pre->relu, mean/logvar, reparam, prev update ----
__global__ void k_head(const float* __restrict__ pw, const float* __restrict__ pb,
                       const float* __restrict__ mw, const float* __restrict__ mb,
                       const float* __restrict__ sw, const float* __restrict__ sb,
                       const float* __restrict__ eps, float* __restrict__ out, int blk) {
    __shared__ float sm[256], ss[256];
    int n = blockIdx.x, o = threadIdx.x;
    const float* h = g_hA + n * 128;   // layer 8 output lands in g_hA
    const float* w = pw + o * 128;
    float s = pb[o];
#pragma unroll
    for (int k = 0; k < 128; k++) s += h[k] * w[k];
    s = fmaxf(s, 0.f);
    sm[o] = s * mw[o];
    ss[o] = s * sw[o];
    __syncthreads();
    for (int st = 128; st > 0; st >>= 1) {
        if (o < st) { sm[o] += sm[o + st]; ss[o] += ss[o + st]; }
        __syncthreads();
    }
    if (o == 0) {
        float mean = sm[0] + mb[0];
        float logv = ss[0] + sb[0];
        float nx = eps[n] * expf(0.5f * logv) + mean;
        out[800 + n]  = mean;    // final block's write wins (sequential stream)
        out[1600 + n] = logv;
        if (n >= 288) out[2400 + blk * 512 + (n - 288)] = nx;
        g_prev[512 + n] = nx;    // feed next block
    }
}

// ------------------------------ launcher ---------------------------------
extern "C" void kernel_launch(void* const* d_in, const int* in_sizes, int n_in,
                              void* d_out, int out_size) {
    const float* mgc       = (const float*)d_in[0];
    const float* signal    = (const float*)d_in[1];
    const float* cond_w    = (const float*)d_in[2];
    const float* cond_b    = (const float*)d_in[3];
    const float* conv0_w   = (const float*)d_in[4];
    const float* conv0_b   = (const float*)d_in[5];
    const float* convL_w   = (const float*)d_in[6];
    const float* convL_b   = (const float*)d_in[7];
    const float* condlin_w = (const float*)d_in[8];
    const float* condlin_b = (const float*)d_in[9];
    const float* pre_w     = (const float*)d_in[10];
    const float* pre_b     = (const float*)d_in[11];
    const float* mean_w    = (const float*)d_in[12];
    const float* mean_b    = (const float*)d_in[13];
    const float* std_w     = (const float*)d_in[14];
    const float* std_b     = (const float*)d_in[15];
    const float* eps       = (const float*)d_in[16];
    float* out = (float*)d_out;

    k_init<<<6, 256>>>(signal, out);
    k_cond<<<188, 256>>>(mgc, cond_w, cond_b);
    k_ciall<<<dim3(72, 25), 128>>>(condlin_w, condlin_b);
    k_wprep<<<12288, 256>>>(convL_w, convL_b);

    for (int blk = 0; blk < NBLK; blk++) {
        k_layer0<<<102400, 256>>>(conv0_w + blk * 768, conv0_b + blk * 384, blk);
        for (int l = 1; l <= 8; l++) {
            int logL = 8 - l;
            int M = 800 << logL;
            dim3 grid((M + 127) / 128, 4);
            k_layer<<<grid, 256>>>(blk, l, M, logL);
        }
        k_head<<<800, 256>>>(pre_w + blk * 256 * 128, pre_b + blk * 256,
                             mean_w + blk * 256, mean_b + blk,
                             std_w + blk * 256, std_b + blk,
                             eps + blk * 800, out, blk);
    }
}

// round 3
// speedup vs baseline: 2.1549x; 2.1549x over previous
#include <cuda_runtime.h>
#include <cuda_bf16.h>
#include <math.h>
#include <stdint.h>

#define SQC 0.70710678118f

// ---------------- device scratch ----------------
__device__ float g_prev[1312];
__device__ float g_cond[48000];
__device__ float g_ciAll[4 * 9 * 2 * 800 * 128];
__device__ float g_bp[4 * 8 * 384];
__device__ __nv_bfloat16 g_WpH[4 * 8 * 384 * 256];
__device__ __nv_bfloat16 g_WpL[4 * 8 * 384 * 256];
__device__ __nv_bfloat16 g_hAH[800 * 256 * 128];
__device__ __nv_bfloat16 g_hAL[800 * 256 * 128];
__device__ __nv_bfloat16 g_hBH[800 * 256 * 128];
__device__ __nv_bfloat16 g_hBL[800 * 256 * 128];

// ---------------- helpers ----------------
__device__ __forceinline__ uint32_t smem_u32(const void* p) {
    uint32_t a;
    asm("{ .reg .u64 t; cvta.to.shared.u64 t, %1; cvt.u32.u64 %0, t; }" : "=r"(a) : "l"(p));
    return a;
}
__device__ __forceinline__ void cpa16(uint32_t dst, const void* src) {
    asm volatile("cp.async.cg.shared.global [%0], [%1], 16;"
                 :: "r"(dst), "l"((unsigned long long)__cvta_generic_to_global(src)));
}
__device__ __forceinline__ void mma_bf16(float* c, const uint32_t* a, const uint32_t* b) {
    asm volatile("mma.sync.aligned.m16n8k16.row.col.f32.bf16.bf16.f32 "
                 "{%0,%1,%2,%3}, {%4,%5,%6,%7}, {%8,%9}, {%0,%1,%2,%3};"
                 : "+f"(c[0]), "+f"(c[1]), "+f"(c[2]), "+f"(c[3])
                 : "r"(a[0]), "r"(a[1]), "r"(a[2]), "r"(a[3]), "r"(b[0]), "r"(b[1]));
}
__device__ __forceinline__ uint32_t lds32(const char* base, int off) {
    return *(const uint32_t*)(base + off);
}

// ---------------- init ----------------
__global__ void k_init(const float* __restrict__ sig, float* __restrict__ out) {
    int i = blockIdx.x * blockDim.x + threadIdx.x;
    if (i < 1312) g_prev[i] = sig[i];
    if (i < 800)  out[i] = sig[512 + i];
}

// ---------------- cond = tanh(mgc @ cond_w.T + b) ----------------
__global__ void k_cond(const float* __restrict__ mgc, const float* __restrict__ cw,
                       const float* __restrict__ cb) {
    int id = blockIdx.x * 256 + threadIdx.x;
    if (id >= 4 * 12000) return;
    int t = id / 12000, w = id % 12000;
    const float* wr = cw + w * 60;
    const float* mg = mgc + t * 60;
    float s = cb[w];
#pragma unroll
    for (int k = 0; k < 60; k++) s += mg[k] * wr[k];
    g_cond[(t * 200 + w / 60) * 60 + (w % 60)] = tanhf(s);
}

// ---------------- cond-linear projections [72,800,128] ----------------
__global__ void k_ciall(const float* __restrict__ clw, const float* __restrict__ clb) {
    __shared__ float cs[32][60];
    int wg = blockIdx.x, nt = blockIdx.y, f = threadIdx.x;
    for (int i = f; i < 32 * 60; i += 128)
        cs[i / 60][i % 60] = g_cond[(nt * 32 + i / 60) * 60 + (i % 60)];
    __syncthreads();
    float wr[60];
    const float* wsrc = clw + (wg * 128 + f) * 60;
#pragma unroll
    for (int k = 0; k < 60; k++) wr[k] = wsrc[k];
    float b = clb[wg * 128 + f];
    for (int nn = 0; nn < 32; nn++) {
        float s = b;
#pragma unroll
        for (int k = 0; k < 60; k++) s += wr[k] * cs[nn][k];
        g_ciAll[(wg * 800 + nt * 32 + nn) * 128 + f] = s;
    }
}

// ---------------- weight split/permute: Wp[bl][f*3+t][kk*128+c] ----------------
__global__ void k_wprep(const float* __restrict__ wL, const float* __restrict__ bL) {
    int idx = blockIdx.x * 256 + threadIdx.x;
    const int total = 4 * 8 * 384 * 256;
    if (idx < total) {
        int k  = idx & 255;
        int r  = (idx >> 8) % 384;
        int bl = idx / (384 * 256);
        int f = r / 3, t = r % 3, kk = k >> 7, c = k & 127;
        float w = wL[(((bl * 3 + t) * 128 + f) * 128 + c) * 2 + kk];
        __nv_bfloat16 hi = __float2bfloat16(w);
        g_WpH[idx] = hi;
        g_WpL[idx] = __float2bfloat16(w - __bfloat162float(hi));
    }
    if (idx < 4 * 8 * 384) {
        int r = idx % 384, bl = idx / 384;
        g_bp[idx] = bL[(bl * 3 + (r % 3)) * 128 + (r / 3)];
    }
}

// ---------------- layer 0 (Cin=1), writes bf16 hi/lo ----------------
__global__ void k_layer0(const float* __restrict__ w0, const float* __restrict__ b0, int blk) {
    int gid = blockIdx.x * 256 + threadIdx.x;
    int m = gid >> 7, f = gid & 127;
    if (m >= 800 * 256) return;
    int n = m >> 8, j = m & 255;
    const float* ci = g_ciAll + (size_t)(blk * 9 * 2) * 102400;
    const float* cg = ci + 102400;
    float a = g_prev[n + 2 * j], b = g_prev[n + 2 * j + 1];
    float o0 = a * w0[f * 2]             + b * w0[f * 2 + 1]             + b0[f];
    float o1 = a * w0[(128 + f) * 2]     + b * w0[(128 + f) * 2 + 1]     + b0[128 + f];
    float o2 = a * w0[(256 + f) * 2]     + b * w0[(256 + f) * 2 + 1]     + b0[256 + f];
    float it = tanhf(o0 + ci[n * 128 + f]);
    float gt = 1.f / (1.f + expf(-(o1 + cg[n * 128 + f])));
    float x = (it * gt + o2) * SQC;
    __nv_bfloat16 hi = __float2bfloat16(x);
    g_hAH[gid] = hi;
    g_hAL[gid] = __float2bfloat16(x - __bfloat162float(hi));
}

// ------------- layers 1..8: mma.sync bf16x3 GEMM + fused gating -------------
// CTA: 128 (m) x 96 (gates = 32 f-triples); K=256 in 8 chunks of 32.
// 8 warps: warpM in {0,1} (64 rows), warpN in {0..3} (24 gates).
#define AS_BYTES (2 * 2 * 128 * 80)   // 40960
#define BS_BYTES (2 * 2 * 96 * 80)    // 30720
#define SMEM_DYN (AS_BYTES + BS_BYTES)

__device__ __forceinline__ void load_tile(
    char* As, char* Bs, int buf,
    const __nv_bfloat16* AH, const __nv_bfloat16* AL,
    const __nv_bfloat16* BH, const __nv_bfloat16* BL,
    int m0, int r0, int k0, int tid)
{
    uint32_t asb = smem_u32(As), bsb = smem_u32(Bs);
#pragma unroll
    for (int it = 0; it < 7; it++) {
        int c = tid + it * 256;
        if (c < 1024) {
            int prec = c >> 9, rem = c & 511, row = rem >> 2, seg = rem & 3;
            const __nv_bfloat16* src = (prec ? AL : AH) + (size_t)(m0 + row) * 256 + k0 + seg * 8;
            cpa16(asb + ((buf * 2 + prec) * 128 + row) * 80 + seg * 16, src);
        } else {
            int j = c - 1024;
            int prec = (j >= 384) ? 1 : 0;
            int rem  = (j >= 384) ? j - 384 : j;
            int row = rem >> 2, seg = rem & 3;
            const __nv_bfloat16* src = (prec ? BL : BH) + (size_t)(r0 + row) * 256 + k0 + seg * 8;
            cpa16(bsb + ((buf * 2 + prec) * 96 + row) * 80 + seg * 16, src);
        }
    }
    asm volatile("cp.async.commit_group;");
}

__global__ void __launch_bounds__(256, 2)
k_layer_mma(int dir, int wtile, int lidx, int M, int logL) {
    extern __shared__ __align__(16) char sm[];
    char* As = sm;
    char* Bs = sm + AS_BYTES;
    float* Cs = (float*)sm;                  // [128][100], reused after mainloop

    const int tid  = threadIdx.x;
    const int lane = tid & 31, wid = tid >> 5;
    const int gid  = lane >> 2, tig = lane & 3;
    const int warpM = wid & 1, warpN = wid >> 1;

    const int m0 = blockIdx.y * 128;
    const int r0 = blockIdx.x * 96;

    const __nv_bfloat16* AH = dir ? g_hBH : g_hAH;
    const __nv_bfloat16* AL = dir ? g_hBL : g_hAL;
    __nv_bfloat16* oH = dir ? g_hAH : g_hBH;
    __nv_bfloat16* oL = dir ? g_hAL : g_hBL;
    const __nv_bfloat16* BH = g_WpH + (size_t)wtile * 384 * 256;
    const __nv_bfloat16* BL = g_WpL + (size_t)wtile * 384 * 256;

    float acc[4][3][4];
#pragma unroll
    for (int a = 0; a < 4; a++)
#pragma unroll
        for (int b = 0; b < 3; b++)
#pragma unroll
            for (int c = 0; c < 4; c++) acc[a][b][c] = 0.f;

    load_tile(As, Bs, 0, AH, AL, BH, BL, m0, r0, 0, tid);

    for (int ks = 0; ks < 8; ks++) {
        int buf = ks & 1;
        if (ks < 7) {
            load_tile(As, Bs, buf ^ 1, AH, AL, BH, BL, m0, r0, (ks + 1) * 32, tid);
            asm volatile("cp.async.wait_group 1;");
        } else {
            asm volatile("cp.async.wait_group 0;");
        }
        __syncthreads();

        const char* aB = As + ((buf * 2) * 128 + warpM * 64 + gid) * 80 + tig * 4;
        const char* bB = Bs + ((buf * 2) * 96 + warpN * 24 + gid) * 80 + tig * 4;
#pragma unroll
        for (int kf = 0; kf < 2; kf++) {
            uint32_t bH[3][2], bL[3][2];
#pragma unroll
            for (int ni = 0; ni < 3; ni++) {
                int o = ni * 8 * 80 + kf * 32;
                bH[ni][0] = lds32(bB, o);
                bH[ni][1] = lds32(bB, o + 16);
                bL[ni][0] = lds32(bB, o + 96 * 80);
                bL[ni][1] = lds32(bB, o + 96 * 80 + 16);
            }
#pragma unroll
            for (int mi = 0; mi < 4; mi++) {
                int o = mi * 16 * 80 + kf * 32;
                uint32_t aH[4], aL[4];
                aH[0] = lds32(aB, o);       aH[1] = lds32(aB, o + 640);
                aH[2] = lds32(aB, o + 16);  aH[3] = lds32(aB, o + 656);
                aL[0] = lds32(aB, o + 128 * 80);        aL[1] = lds32(aB, o + 128 * 80 + 640);
                aL[2] = lds32(aB, o + 128 * 80 + 16);   aL[3] = lds32(aB, o + 128 * 80 + 656);
#pragma unroll
                for (int ni = 0; ni < 3; ni++) {
                    mma_bf16(acc[mi][ni], aH, bH[ni]);
                    mma_bf16(acc[mi][ni], aH, bL[ni]);
                    mma_bf16(acc[mi][ni], aL, bH[ni]);
                }
            }
        }
        __syncthreads();
    }

    // ---- epilogue: accums -> smem -> fused gating -> bf16 hi/lo out ----
#pragma unroll
    for (int mi = 0; mi < 4; mi++)
#pragma unroll
        for (int ni = 0; ni < 3; ni++) {
            int ml = warpM * 64 + mi * 16 + gid;
            int rl = warpN * 24 + ni * 8 + tig * 2;
            Cs[ml * 100 + rl]           = acc[mi][ni][0];
            Cs[ml * 100 + rl + 1]       = acc[mi][ni][1];
            Cs[(ml + 8) * 100 + rl]     = acc[mi][ni][2];
            Cs[(ml + 8) * 100 + rl + 1] = acc[mi][ni][3];
        }
    __syncthreads();

    int fl = tid & 31;
    int fg = blockIdx.x * 32 + fl;
    const float* bp = g_bp + wtile * 384 + r0;
    float b0 = bp[fl * 3], b1 = bp[fl * 3 + 1], b2 = bp[fl * 3 + 2];
    const float* ci = g_ciAll + (size_t)lidx * 2 * 102400;
    const float* cg = ci + 102400;
#pragma unroll
    for (int i = 0; i < 16; i++) {
        int ml = (tid >> 5) + i * 8;
        int m = m0 + ml;
        if (m < M) {
            int n = m >> logL;
            float o0 = Cs[ml * 100 + fl * 3]     + b0 + ci[n * 128 + fg];
            float o1 = Cs[ml * 100 + fl * 3 + 1] + b1 + cg[n * 128 + fg];
            float o2 = Cs[ml * 100 + fl * 3 + 2] + b2;
            float x = (tanhf(o0) * (1.f / (1.f + expf(-o1))) + o2) * SQC;
            __nv_bfloat16 hi = __float2bfloat16(x);
            oH[(size_t)m * 128 + fg] = hi;
            oL[(size_t)m * 128 + fg] = __float2bfloat16(x - __bfloat162float(hi));
        }
    }
}

// ---------------- heads ----------------
__global__ void k_head(const float* __restrict__ pw, const float* __restrict__ pb,
                       const float* __restrict__ mw, const float* __restrict__ mb,
                       const float* __restrict__ sw, const float* __restrict__ sb,
                       const float* __restrict__ eps, float* __restrict__ out, int blk) {
    __shared__ float sm_[256], ss_[256];
    int n = blockIdx.x, o = threadIdx.x;
    const __nv_bfloat16* hh = g_hAH + n * 128;
    const __nv_bfloat16* hl = g_hAL + n * 128;
    const float* w = pw + o * 128;
    float s = pb[o];
#pragma unroll
    for (int k = 0; k < 128; k++)
        s += (__bfloat162float(hh[k]) + __bfloat162float(hl[k])) * w[k];
    s = fmaxf(s, 0.f);
    sm_[o] = s * mw[o];
    ss_[o] = s * sw[o];
    __syncthreads();
    for (int st = 128; st > 0; st >>= 1) {
        if (o < st) { sm_[o] += sm_[o + st]; ss_[o] += ss_[o + st]; }
        __syncthreads();
    }
    if (o == 0) {
        float mean = sm_[0] + mb[0];
        float logv = ss_[0] + sb[0];
        float nx = eps[n] * expf(0.5f * logv) + mean;
        out[800 + n]  = mean;
        out[1600 + n] = logv;
        if (n >= 288) out[2400 + blk * 512 + (n - 288)] = nx;
        g_prev[512 + n] = nx;
    }
}

// ---------------- launcher ----------------
extern "C" void kernel_launch(void* const* d_in, const int* in_sizes, int n_in,
                              void* d_out, int out_size) {
    const float* mgc       = (const float*)d_in[0];
    const float* signal    = (const float*)d_in[1];
    const float* cond_w    = (const float*)d_in[2];
    const float* cond_b    = (const float*)d_in[3];
    const float* conv0_w   = (const float*)d_in[4];
    const float* conv0_b   = (const float*)d_in[5];
    const float* convL_w   = (const float*)d_in[6];
    const float* convL_b   = (const float*)d_in[7];
    const float* condlin_w = (const float*)d_in[8];
    const float* condlin_b = (const float*)d_in[9];
    const float* pre_w     = (const float*)d_in[10];
    const float* pre_b     = (const float*)d_in[11];
    const float* mean_w    = (const float*)d_in[12];
    const float* mean_b    = (const float*)d_in[13];
    const float* std_w     = (const float*)d_in[14];
    const float* std_b     = (const float*)d_in[15];
    const float* eps       = (const float*)d_in[16];
    float* out = (float*)d_out;

    static bool attrSet = false;
    if (!attrSet) {
        cudaFuncSetAttribute(k_layer_mma, cudaFuncAttributeMaxDynamicSharedMemorySize, SMEM_DYN);
        attrSet = true;
    }

    k_init<<<6, 256>>>(signal, out);
    k_cond<<<188, 256>>>(mgc, cond_w, cond_b);
    k_ciall<<<dim3(72, 25), 128>>>(condlin_w, condlin_b);
    k_wprep<<<12288, 256>>>(convL_w, convL_b);

    for (int blk = 0; blk < 4; blk++) {
        k_layer0<<<102400, 256>>>(conv0_w + blk * 768, conv0_b + blk * 384, blk);
        for (int l = 1; l <= 8; l++) {
            int logL = 8 - l;
            int M = 800 << logL;
            int tiles = (M + 127) / 128;
            k_layer_mma<<<dim3(4, tiles), 256, SMEM_DYN>>>(
                (l & 1) ? 0 : 1, blk * 8 + l - 1, blk * 9 + l, M, logL);
        }
        k_head<<<800, 256>>>(pre_w + blk * 256 * 128, pre_b + blk * 256,
                             mean_w + blk * 256, mean_b + blk,
                             std_w + blk * 256, std_b + blk,
                             eps + blk * 800, out, blk);
    }
}

// round 4
// speedup vs baseline: 2.3024x; 1.0685x over previous
#include <cuda_runtime.h>
#include <cuda_fp16.h>
#include <math.h>
#include <stdint.h>

#define SQC 0.70710678118f

// ---------------- device scratch ----------------
__device__ float g_prev[1312];
__device__ float g_cond[48000];
__device__ float g_ciAll[4 * 9 * 2 * 800 * 128];
__device__ float g_bp[4 * 8 * 384];
__device__ __half g_WpH[4 * 8 * 384 * 256];
__device__ __half g_WpL[4 * 8 * 384 * 256];
__device__ __half g_hA[800 * 256 * 128];
__device__ __half g_hB[800 * 256 * 128];

// ---------------- helpers ----------------
__device__ __forceinline__ uint32_t smem_u32(const void* p) {
    uint32_t a;
    asm("{ .reg .u64 t; cvta.to.shared.u64 t, %1; cvt.u32.u64 %0, t; }" : "=r"(a) : "l"(p));
    return a;
}
__device__ __forceinline__ void cpa16(uint32_t dst, const void* src) {
    asm volatile("cp.async.cg.shared.global [%0], [%1], 16;"
                 :: "r"(dst), "l"((unsigned long long)__cvta_generic_to_global(src)));
}
__device__ __forceinline__ void mma_f16(float* c, const uint32_t* a, const uint32_t* b) {
    asm volatile("mma.sync.aligned.m16n8k16.row.col.f32.f16.f16.f32 "
                 "{%0,%1,%2,%3}, {%4,%5,%6,%7}, {%8,%9}, {%0,%1,%2,%3};"
                 : "+f"(c[0]), "+f"(c[1]), "+f"(c[2]), "+f"(c[3])
                 : "r"(a[0]), "r"(a[1]), "r"(a[2]), "r"(a[3]), "r"(b[0]), "r"(b[1]));
}
#define LDM4(r0, r1, r2, r3, addr) \
    asm volatile("ldmatrix.sync.aligned.m8n8.x4.shared.b16 {%0,%1,%2,%3}, [%4];" \
                 : "=r"(r0), "=r"(r1), "=r"(r2), "=r"(r3) : "r"(addr))

// ---------------- prep 0: init + cond ----------------
__global__ void k_prep0(const float* __restrict__ sig, float* __restrict__ out,
                        const float* __restrict__ mgc, const float* __restrict__ cw,
                        const float* __restrict__ cb) {
    int b = blockIdx.x, tid = threadIdx.x;
    if (b == 188) {
        for (int i = tid; i < 1312; i += 256) g_prev[i] = sig[i];
        for (int i = tid; i < 800; i += 256) out[i] = sig[512 + i];
        return;
    }
    int id = b * 256 + tid;
    if (id >= 48000) return;
    int t = id / 12000, w = id % 12000;
    const float* wr = cw + w * 60;
    const float* mg = mgc + t * 60;
    float s = cb[w];
#pragma unroll
    for (int k = 0; k < 60; k++) s += mg[k] * wr[k];
    g_cond[(t * 200 + w / 60) * 60 + (w % 60)] = tanhf(s);
}

// ---------------- prep 1: ciall + wprep (fused) ----------------
__global__ void k_prep1(const float* __restrict__ clw, const float* __restrict__ clb,
                        const float* __restrict__ wL, const float* __restrict__ bL) {
    int b = blockIdx.x, tid = threadIdx.x;
    if (b < 1800) {
        __shared__ float cs[32][60];
        int wg = b / 25, nt = b % 25;
        for (int i = tid; i < 32 * 60; i += 256)
            cs[i / 60][i % 60] = g_cond[(nt * 32 + i / 60) * 60 + (i % 60)];
        __syncthreads();
        int f = tid & 127, nh = tid >> 7;
        float wr[60];
        const float* wsrc = clw + (wg * 128 + f) * 60;
#pragma unroll
        for (int k = 0; k < 60; k++) wr[k] = wsrc[k];
        float bia = clb[wg * 128 + f];
        for (int nn = nh * 16; nn < nh * 16 + 16; nn++) {
            float s = bia;
#pragma unroll
            for (int k = 0; k < 60; k++) s += wr[k] * cs[nn][k];
            g_ciAll[(wg * 800 + nt * 32 + nn) * 128 + f] = s;
        }
        return;
    }
    int idx = (b - 1800) * 256 + tid;
    const int total = 4 * 8 * 384 * 256;
    if (idx < total) {
        int k  = idx & 255;
        int r  = (idx >> 8) % 384;
        int bl = idx / (384 * 256);
        int f = r / 3, t = r % 3, kk = k >> 7, c = k & 127;
        float w = wL[(((bl * 3 + t) * 128 + f) * 128 + c) * 2 + kk];
        __half hi = __float2half_rn(w);
        g_WpH[idx] = hi;
        g_WpL[idx] = __float2half_rn(w - __half2float(hi));
    }
    if (idx < 4 * 8 * 384) {
        int r = idx % 384, bl = idx / 384;
        g_bp[idx] = bL[(bl * 3 + (r % 3)) * 128 + (r / 3)];
    }
}

// ---------------- layer 0 (Cin=1) ----------------
__global__ void k_layer0(const float* __restrict__ w0, const float* __restrict__ b0, int blk) {
    int gid = blockIdx.x * 256 + threadIdx.x;
    int m = gid >> 7, f = gid & 127;
    if (m >= 800 * 256) return;
    int n = m >> 8, j = m & 255;
    const float* ci = g_ciAll + (size_t)(blk * 9 * 2) * 102400;
    const float* cg = ci + 102400;
    float a = g_prev[n + 2 * j], b = g_prev[n + 2 * j + 1];
    float o0 = a * w0[f * 2]         + b * w0[f * 2 + 1]         + b0[f];
    float o1 = a * w0[(128 + f) * 2] + b * w0[(128 + f) * 2 + 1] + b0[128 + f];
    float o2 = a * w0[(256 + f) * 2] + b * w0[(256 + f) * 2 + 1] + b0[256 + f];
    float it = tanhf(o0 + ci[n * 128 + f]);
    float gt = 1.f / (1.f + expf(-(o1 + cg[n * 128 + f])));
    g_hA[gid] = __float2half_rn((it * gt + o2) * SQC);
}

// ------------- layers 1..8: mma.sync fp16 2-term GEMM + fused gating -------------
// CTA: 128(m) x 192(gates = 64 f-triples); K=256 in 4 chunks of 64.
// 8 warps: warpM in {0,1} (64 rows), warpN in {0..3} (48 gates).
#define BMx 128
#define BNx 192
#define BKx 64
#define APITCH 144
#define ABUF (BMx * APITCH)          /* 18432 */
#define BHALF (BNx * APITCH)         /* 27648 */
#define BUFSZ (ABUF + 2 * BHALF)     /* 73728 */
#define SMEM_DYN (2 * BUFSZ)         /* 147456 */

__device__ __forceinline__ void load_tile(
    uint32_t smb, int buf, const __half* A, const __half* BH, const __half* BL,
    int m0, long r0, int k0, int tid)
{
    uint32_t base = smb + buf * BUFSZ;
#pragma unroll
    for (int it = 0; it < 16; it++) {
        int c = tid + it * 256;
        if (c < 1024) {
            int row = c >> 3, seg = c & 7;
            cpa16(base + row * APITCH + seg * 16,
                  A + (size_t)(m0 + row) * 256 + k0 + seg * 8);
        } else {
            int j = c - 1024;
            int prec = (j >= 1536) ? 1 : 0;
            int rem  = prec ? j - 1536 : j;
            int row = rem >> 3, seg = rem & 7;
            const __half* src = (prec ? BL : BH) + (r0 + row) * 256 + k0 + seg * 8;
            cpa16(base + ABUF + prec * BHALF + row * APITCH + seg * 16, src);
        }
    }
    asm volatile("cp.async.commit_group;");
}

__global__ void __launch_bounds__(256)
k_layer_mma(int dir, int wtile, int lidx, int M, int logL) {
    extern __shared__ __align__(16) char sm[];
    float* Cs = (float*)sm;      // [128][200] floats, reused after mainloop
    uint32_t smb = smem_u32(sm);

    const int tid  = threadIdx.x;
    const int lane = tid & 31, wid = tid >> 5;
    const int gid  = lane >> 2, tig = lane & 3;
    const int warpM = wid & 1, warpN = wid >> 1;

    const int ntile = blockIdx.x;            // 0..1
    const int m0 = blockIdx.y * BMx;
    const long r0 = (long)wtile * 384 + ntile * 192;

    const __half* A = dir ? g_hB : g_hA;
    __half* O       = dir ? g_hA : g_hB;

    float acc[4][6][4];
#pragma unroll
    for (int a = 0; a < 4; a++)
#pragma unroll
        for (int b = 0; b < 6; b++)
#pragma unroll
            for (int c = 0; c < 4; c++) acc[a][b][c] = 0.f;

    load_tile(smb, 0, A, g_WpH, g_WpL, m0, r0, 0, tid);

    // per-warp ldmatrix lane addresses (buffer-relative)
    const int aRow = warpM * 64 + (lane & 15);
    const int aByt = (lane >> 4) * 16;
    const int bRow = warpN * 48 + ((lane >> 4) << 3) + (lane & 7);
    const int bByt = ((lane >> 3) & 1) * 16;

    for (int ks = 0; ks < 4; ks++) {
        int buf = ks & 1;
        if (ks < 3) {
            load_tile(smb, buf ^ 1, A, g_WpH, g_WpL, m0, r0, (ks + 1) * BKx, tid);
            asm volatile("cp.async.wait_group 1;");
        } else {
            asm volatile("cp.async.wait_group 0;");
        }
        __syncthreads();

        uint32_t aBase = smb + buf * BUFSZ + aRow * APITCH + aByt;
        uint32_t bBase = smb + buf * BUFSZ + ABUF + bRow * APITCH + bByt;
#pragma unroll
        for (int kf = 0; kf < 4; kf++) {
            uint32_t bf[2][6][2];
#pragma unroll
            for (int prec = 0; prec < 2; prec++)
#pragma unroll
                for (int p2 = 0; p2 < 3; p2++) {
                    uint32_t ad = bBase + prec * BHALF + p2 * 16 * APITCH + kf * 32;
                    LDM4(bf[prec][2 * p2][0], bf[prec][2 * p2][1],
                         bf[prec][2 * p2 + 1][0], bf[prec][2 * p2 + 1][1], ad);
                }
#pragma unroll
            for (int mi = 0; mi < 4; mi++) {
                uint32_t af[4];
                LDM4(af[0], af[1], af[2], af[3], aBase + mi * 16 * APITCH + kf * 32);
#pragma unroll
                for (int ni = 0; ni < 6; ni++) {
                    mma_f16(acc[mi][ni], af, bf[0][ni]);
                    mma_f16(acc[mi][ni], af, bf[1][ni]);
                }
            }
        }
        __syncthreads();
    }

    // ---- epilogue: accums -> smem -> fused gating -> fp16 out ----
#pragma unroll
    for (int mi = 0; mi < 4; mi++)
#pragma unroll
        for (int ni = 0; ni < 6; ni++) {
            int ml = warpM * 64 + mi * 16 + gid;
            int rl = warpN * 48 + ni * 8 + tig * 2;
            Cs[ml * 200 + rl]           = acc[mi][ni][0];
            Cs[ml * 200 + rl + 1]       = acc[mi][ni][1];
            Cs[(ml + 8) * 200 + rl]     = acc[mi][ni][2];
            Cs[(ml + 8) * 200 + rl + 1] = acc[mi][ni][3];
        }
    __syncthreads();

    const int fl = tid & 63;
    const int fg = ntile * 64 + fl;
    const float* bpp = g_bp + wtile * 384 + ntile * 192;
    float b0 = bpp[fl * 3], b1 = bpp[fl * 3 + 1], b2 = bpp[fl * 3 + 2];
    const float* ci = g_ciAll + (size_t)lidx * 2 * 102400;
    const float* cg = ci + 102400;
#pragma unroll
    for (int i = 0; i < 32; i++) {
        int ml = (tid >> 6) + i * 4;
        int m = m0 + ml;
        if (m < M) {
            int n = m >> logL;
            float o0 = Cs[ml * 200 + fl * 3]     + b0 + ci[n * 128 + fg];
            float o1 = Cs[ml * 200 + fl * 3 + 1] + b1 + cg[n * 128 + fg];
            float o2 = Cs[ml * 200 + fl * 3 + 2] + b2;
            float x = (tanhf(o0) * (1.f / (1.f + expf(-o1))) + o2) * SQC;
            O[(size_t)m * 128 + fg] = __float2half_rn(x);
        }
    }
}

// ---------------- heads ----------------
__global__ void k_head(const float* __restrict__ pw, const float* __restrict__ pb,
                       const float* __restrict__ mw, const float* __restrict__ mb,
                       const float* __restrict__ sw, const float* __restrict__ sb,
                       const float* __restrict__ eps, float* __restrict__ out, int blk) {
    __shared__ float sm_[256], ss_[256];
    int n = blockIdx.x, o = threadIdx.x;
    const __half* h = g_hA + n * 128;   // layer 8 output lands in g_hA (dir=1 on l=8)
    const float* w = pw + o * 128;
    float s = pb[o];
#pragma unroll
    for (int k = 0; k < 128; k++) s += __half2float(h[k]) * w[k];
    s = fmaxf(s, 0.f);
    sm_[o] = s * mw[o];
    ss_[o] = s * sw[o];
    __syncthreads();
    for (int st = 128; st > 0; st >>= 1) {
        if (o < st) { sm_[o] += sm_[o + st]; ss_[o] += ss_[o + st]; }
        __syncthreads();
    }
    if (o == 0) {
        float mean = sm_[0] + mb[0];
        float logv = ss_[0] + sb[0];
        float nx = eps[n] * expf(0.5f * logv) + mean;
        out[800 + n]  = mean;
        out[1600 + n] = logv;
        if (n >= 288) out[2400 + blk * 512 + (n - 288)] = nx;
        g_prev[512 + n] = nx;
    }
}

// ---------------- launcher ----------------
extern "C" void kernel_launch(void* const* d_in, const int* in_sizes, int n_in,
                              void* d_out, int out_size) {
    const float* mgc       = (const float*)d_in[0];
    const float* signal    = (const float*)d_in[1];
    const float* cond_w    = (const float*)d_in[2];
    const float* cond_b    = (const float*)d_in[3];
    const float* conv0_w   = (const float*)d_in[4];
    const float* conv0_b   = (const float*)d_in[5];
    const float* convL_w   = (const float*)d_in[6];
    const float* convL_b   = (const float*)d_in[7];
    const float* condlin_w = (const float*)d_in[8];
    const float* condlin_b = (const float*)d_in[9];
    const float* pre_w     = (const float*)d_in[10];
    const float* pre_b     = (const float*)d_in[11];
    const float* mean_w    = (const float*)d_in[12];
    const float* mean_b    = (const float*)d_in[13];
    const float* std_w     = (const float*)d_in[14];
    const float* std_b     = (const float*)d_in[15];
    const float* eps       = (const float*)d_in[16];
    float* out = (float*)d_out;

    static bool attrSet = false;
    if (!attrSet) {
        cudaFuncSetAttribute(k_layer_mma, cudaFuncAttributeMaxDynamicSharedMemorySize, SMEM_DYN);
        attrSet = true;
    }

    k_prep0<<<189, 256>>>(signal, out, mgc, cond_w, cond_b);
    k_prep1<<<1800 + 12288, 256>>>(condlin_w, condlin_b, convL_w, convL_b);

    for (int blk = 0; blk < 4; blk++) {
        k_layer0<<<102400, 256>>>(conv0_w + blk * 768, conv0_b + blk * 384, blk);
        for (int l = 1; l <= 8; l++) {
            int logL = 8 - l;
            int M = 800 << logL;
            int tiles = (M + BMx - 1) / BMx;
            k_layer_mma<<<dim3(2, tiles), 256, SMEM_DYN>>>(
                (l & 1) ? 0 : 1, blk * 8 + l - 1, blk * 9 + l, M, logL);
        }
        k_head<<<800, 256>>>(pre_w + blk * 256 * 128, pre_b + blk * 256,
                             mean_w + blk * 256, mean_b + blk,
                             std_w + blk * 256, std_b + blk,
                             eps + blk * 800, out, blk);
    }
}

// round 5
// speedup vs baseline: 2.5503x; 1.1077x over previous
#include <cuda_runtime.h>
#include <cuda_fp16.h>
#include <math.h>
#include <stdint.h>

#define SQC 0.70710678118f

// ---------------- device scratch ----------------
__device__ float g_prev[1312];
__device__ float g_cond[48000];
__device__ float g_ciAll[4 * 9 * 2 * 800 * 128];
__device__ float g_bp[4 * 8 * 384];
__device__ __half g_WpH[4 * 8 * 384 * 256];
__device__ __half g_WpL[4 * 8 * 384 * 256];
__device__ __half g_hA[800 * 256 * 128];
__device__ __half g_hB[800 * 256 * 128];

// ---------------- helpers ----------------
__device__ __forceinline__ uint32_t smem_u32(const void* p) {
    uint32_t a;
    asm("{ .reg .u64 t; cvta.to.shared.u64 t, %1; cvt.u32.u64 %0, t; }" : "=r"(a) : "l"(p));
    return a;
}
__device__ __forceinline__ void cpa16(uint32_t dst, const void* src) {
    asm volatile("cp.async.cg.shared.global [%0], [%1], 16;"
                 :: "r"(dst), "l"((unsigned long long)__cvta_generic_to_global(src)));
}
__device__ __forceinline__ void mma_f16(float* c, const uint32_t* a, const uint32_t* b) {
    asm volatile("mma.sync.aligned.m16n8k16.row.col.f32.f16.f16.f32 "
                 "{%0,%1,%2,%3}, {%4,%5,%6,%7}, {%8,%9}, {%0,%1,%2,%3};"
                 : "+f"(c[0]), "+f"(c[1]), "+f"(c[2]), "+f"(c[3])
                 : "r"(a[0]), "r"(a[1]), "r"(a[2]), "r"(a[3]), "r"(b[0]), "r"(b[1]));
}
#define LDM4(r0, r1, r2, r3, addr) \
    asm volatile("ldmatrix.sync.aligned.m8n8.x4.shared.b16 {%0,%1,%2,%3}, [%4];" \
                 : "=r"(r0), "=r"(r1), "=r"(r2), "=r"(r3) : "r"(addr))

__device__ __forceinline__ float fsig(float x) { return __fdividef(1.f, 1.f + __expf(-x)); }
__device__ __forceinline__ float fth(float x)  { return 2.f * fsig(2.f * x) - 1.f; }

// ---------------- prep 0: init + cond ----------------
__global__ void k_prep0(const float* __restrict__ sig, float* __restrict__ out,
                        const float* __restrict__ mgc, const float* __restrict__ cw,
                        const float* __restrict__ cb) {
    int b = blockIdx.x, tid = threadIdx.x;
    if (b == 188) {
        for (int i = tid; i < 1312; i += 256) g_prev[i] = sig[i];
        for (int i = tid; i < 800; i += 256) out[i] = sig[512 + i];
        return;
    }
    int id = b * 256 + tid;
    if (id >= 48000) return;
    int t = id / 12000, w = id % 12000;
    const float* wr = cw + w * 60;
    const float* mg = mgc + t * 60;
    float s = cb[w];
#pragma unroll
    for (int k = 0; k < 60; k++) s += mg[k] * wr[k];
    g_cond[(t * 200 + w / 60) * 60 + (w % 60)] = tanhf(s);
}

// ---------------- prep 1: ciall + wprep (fused) ----------------
__global__ void k_prep1(const float* __restrict__ clw, const float* __restrict__ clb,
                        const float* __restrict__ wL, const float* __restrict__ bL) {
    int b = blockIdx.x, tid = threadIdx.x;
    if (b < 1800) {
        __shared__ float cs[32][60];
        int wg = b / 25, nt = b % 25;
        for (int i = tid; i < 32 * 60; i += 256)
            cs[i / 60][i % 60] = g_cond[(nt * 32 + i / 60) * 60 + (i % 60)];
        __syncthreads();
        int f = tid & 127, nh = tid >> 7;
        float wr[60];
        const float* wsrc = clw + (wg * 128 + f) * 60;
#pragma unroll
        for (int k = 0; k < 60; k++) wr[k] = wsrc[k];
        float bia = clb[wg * 128 + f];
        for (int nn = nh * 16; nn < nh * 16 + 16; nn++) {
            float s = bia;
#pragma unroll
            for (int k = 0; k < 60; k++) s += wr[k] * cs[nn][k];
            g_ciAll[(wg * 800 + nt * 32 + nn) * 128 + f] = s;
        }
        return;
    }
    int idx = (b - 1800) * 256 + tid;
    const int total = 4 * 8 * 384 * 256;
    if (idx < total) {
        int k  = idx & 255;
        int r  = (idx >> 8) % 384;
        int bl = idx / (384 * 256);
        int f = r / 3, t = r % 3, kk = k >> 7, c = k & 127;
        float w = wL[(((bl * 3 + t) * 128 + f) * 128 + c) * 2 + kk];
        __half hi = __float2half_rn(w);
        g_WpH[idx] = hi;
        g_WpL[idx] = __float2half_rn(w - __half2float(hi));
    }
    if (idx < 4 * 8 * 384) {
        int r = idx % 384, bl = idx / 384;
        g_bp[idx] = bL[(bl * 3 + (r % 3)) * 128 + (r / 3)];
    }
}

// ---------------- layer 0 (Cin=1), half2 stores ----------------
__global__ void k_layer0(const float* __restrict__ w0, const float* __restrict__ b0, int blk) {
    int gid = blockIdx.x * 256 + threadIdx.x;     // pairs: 800*256*64
    if (gid >= 800 * 256 * 64) return;
    int m = gid >> 6, f2 = gid & 63;
    int n = m >> 8, j = m & 255;
    const float* ci = g_ciAll + (size_t)(blk * 9 * 2) * 102400;
    const float* cg = ci + 102400;
    float a = g_prev[n + 2 * j], b = g_prev[n + 2 * j + 1];
    float x2[2];
#pragma unroll
    for (int p = 0; p < 2; p++) {
        int f = f2 * 2 + p;
        float o0 = a * w0[f * 2]         + b * w0[f * 2 + 1]         + b0[f];
        float o1 = a * w0[(128 + f) * 2] + b * w0[(128 + f) * 2 + 1] + b0[128 + f];
        float o2 = a * w0[(256 + f) * 2] + b * w0[(256 + f) * 2 + 1] + b0[256 + f];
        float it = fth(o0 + ci[n * 128 + f]);
        float gt = fsig(o1 + cg[n * 128 + f]);
        x2[p] = (it * gt + o2) * SQC;
    }
    *((__half2*)g_hA + gid) = __floats2half2_rn(x2[0], x2[1]);
}

// ------------- layers 1..8: mma.sync fp16 2-term GEMM + fused gating -------------
// CTA: 64(m) x 192(gates = 64 f-triples); K=256 in 8 chunks of 32.
// 8 warps: warpM in {0,1} (32 rows), warpN in {0..3} (48 gates).
#define BMx 64
#define BKx 32
#define APITCH 80
#define ABUF (BMx * APITCH)            /* 5120 */
#define BROWS 384                      /* 192 hi + 192 lo */
#define BUFSZ (ABUF + BROWS * APITCH)  /* 35840 */
#define SMEM_DYN (2 * BUFSZ)           /* 71680 */

__device__ __forceinline__ void load_tile(
    uint32_t smb, int buf, const __half* A, const __half* BH, const __half* BL,
    int m0, long r0, int k0, int tid)
{
    uint32_t base = smb + buf * BUFSZ;
#pragma unroll
    for (int it = 0; it < 7; it++) {
        int c = tid + it * 256;
        if (c < 256) {
            int row = c >> 2, seg = c & 3;
            cpa16(base + row * APITCH + seg * 16,
                  A + (size_t)(m0 + row) * 256 + k0 + seg * 8);
        } else {
            int j = c - 256;                 // 0..1535
            int row = j >> 2, seg = j & 3;   // row 0..383
            const __half* src = (row < 192)
                ? BH + (r0 + row) * 256 + k0 + seg * 8
                : BL + (r0 + row - 192) * 256 + k0 + seg * 8;
            cpa16(base + ABUF + row * APITCH + seg * 16, src);
        }
    }
    asm volatile("cp.async.commit_group;");
}

__global__ void __launch_bounds__(256, 2)
k_layer_mma(int dir, int wtile, int lidx, int M, int logL) {
    extern __shared__ __align__(16) char sm[];
    float* Cs = (float*)sm;      // [64][200] floats after mainloop (51200 B)
    uint32_t smb = smem_u32(sm);

    const int tid  = threadIdx.x;
    const int lane = tid & 31, wid = tid >> 5;
    const int gid  = lane >> 2, tig = lane & 3;
    const int warpM = wid & 1, warpN = wid >> 1;

    const int ntile = blockIdx.x;            // 0..1
    const int m0 = blockIdx.y * BMx;
    const long r0 = (long)wtile * 384 + ntile * 192;

    const __half* A = dir ? g_hB : g_hA;
    __half* O       = dir ? g_hA : g_hB;

    float acc[2][6][4];
#pragma unroll
    for (int a = 0; a < 2; a++)
#pragma unroll
        for (int b = 0; b < 6; b++)
#pragma unroll
            for (int c = 0; c < 4; c++) acc[a][b][c] = 0.f;

    load_tile(smb, 0, A, g_WpH, g_WpL, m0, r0, 0, tid);

    const int aRow = warpM * 32 + (lane & 15);
    const int aByt = (lane >> 4) * 16;
    const int bRow = warpN * 48 + ((lane >> 4) << 3) + (lane & 7);
    const int bByt = ((lane >> 3) & 1) * 16;

    for (int ks = 0; ks < 8; ks++) {
        int buf = ks & 1;
        asm volatile("cp.async.wait_group 0;");
        __syncthreads();
        if (ks < 7)
            load_tile(smb, buf ^ 1, A, g_WpH, g_WpL, m0, r0, (ks + 1) * BKx, tid);

        uint32_t aBase = smb + buf * BUFSZ + aRow * APITCH + aByt;
        uint32_t bBase = smb + buf * BUFSZ + ABUF + bRow * APITCH + bByt;
#pragma unroll
        for (int kf = 0; kf < 2; kf++) {
            uint32_t bf[2][6][2];
#pragma unroll
            for (int prec = 0; prec < 2; prec++)
#pragma unroll
                for (int p2 = 0; p2 < 3; p2++) {
                    uint32_t ad = bBase + prec * (192 * APITCH) + p2 * 16 * APITCH + kf * 32;
                    LDM4(bf[prec][2 * p2][0], bf[prec][2 * p2][1],
                         bf[prec][2 * p2 + 1][0], bf[prec][2 * p2 + 1][1], ad);
                }
#pragma unroll
            for (int mi = 0; mi < 2; mi++) {
                uint32_t af[4];
                LDM4(af[0], af[1], af[2], af[3], aBase + mi * 16 * APITCH + kf * 32);
#pragma unroll
                for (int ni = 0; ni < 6; ni++) {
                    mma_f16(acc[mi][ni], af, bf[0][ni]);
                    mma_f16(acc[mi][ni], af, bf[1][ni]);
                }
            }
        }
    }
    __syncthreads();

    // ---- epilogue: accums -> smem -> fused gating -> fp16 out ----
#pragma unroll
    for (int mi = 0; mi < 2; mi++)
#pragma unroll
        for (int ni = 0; ni < 6; ni++) {
            int ml = warpM * 32 + mi * 16 + gid;
            int rl = warpN * 48 + ni * 8 + tig * 2;
            Cs[ml * 200 + rl]           = acc[mi][ni][0];
            Cs[ml * 200 + rl + 1]       = acc[mi][ni][1];
            Cs[(ml + 8) * 200 + rl]     = acc[mi][ni][2];
            Cs[(ml + 8) * 200 + rl + 1] = acc[mi][ni][3];
        }
    __syncthreads();

    const int fl = tid & 63;
    const int fg = ntile * 64 + fl;
    const float* bpp = g_bp + wtile * 384 + ntile * 192;
    float b0 = bpp[fl * 3], b1 = bpp[fl * 3 + 1], b2 = bpp[fl * 3 + 2];
    const float* ci = g_ciAll + (size_t)lidx * 2 * 102400;
    const float* cg = ci + 102400;
#pragma unroll
    for (int i = 0; i < 16; i++) {
        int ml = (tid >> 6) + i * 4;
        int m = m0 + ml;
        if (m < M) {
            int n = m >> logL;
            float o0 = Cs[ml * 200 + fl * 3]     + b0 + ci[(size_t)n * 128 + fg];
            float o1 = Cs[ml * 200 + fl * 3 + 1] + b1 + cg[(size_t)n * 128 + fg];
            float o2 = Cs[ml * 200 + fl * 3 + 2] + b2;
            float x = (fth(o0) * fsig(o1) + o2) * SQC;
            O[(size_t)m * 128 + fg] = __float2half_rn(x);
        }
    }
}

// ---------------- heads ----------------
__global__ void k_head(const float* __restrict__ pw, const float* __restrict__ pb,
                       const float* __restrict__ mw, const float* __restrict__ mb,
                       const float* __restrict__ sw, const float* __restrict__ sb,
                       const float* __restrict__ eps, float* __restrict__ out, int blk) {
    __shared__ float sm_[256], ss_[256];
    int n = blockIdx.x, o = threadIdx.x;
    const __half* h = g_hA + n * 128;
    const float* w = pw + o * 128;
    float s = pb[o];
#pragma unroll
    for (int k = 0; k < 128; k++) s += __half2float(h[k]) * w[k];
    s = fmaxf(s, 0.f);
    sm_[o] = s * mw[o];
    ss_[o] = s * sw[o];
    __syncthreads();
    for (int st = 128; st > 0; st >>= 1) {
        if (o < st) { sm_[o] += sm_[o + st]; ss_[o] += ss_[o + st]; }
        __syncthreads();
    }
    if (o == 0) {
        float mean = sm_[0] + mb[0];
        float logv = ss_[0] + sb[0];
        float nx = eps[n] * expf(0.5f * logv) + mean;
        out[800 + n]  = mean;
        out[1600 + n] = logv;
        if (n >= 288) out[2400 + blk * 512 + (n - 288)] = nx;
        g_prev[512 + n] = nx;
    }
}

// ---------------- launcher ----------------
extern "C" void kernel_launch(void* const* d_in, const int* in_sizes, int n_in,
                              void* d_out, int out_size) {
    const float* mgc       = (const float*)d_in[0];
    const float* signal    = (const float*)d_in[1];
    const float* cond_w    = (const float*)d_in[2];
    const float* cond_b    = (const float*)d_in[3];
    const float* conv0_w   = (const float*)d_in[4];
    const float* conv0_b   = (const float*)d_in[5];
    const float* convL_w   = (const float*)d_in[6];
    const float* convL_b   = (const float*)d_in[7];
    const float* condlin_w = (const float*)d_in[8];
    const float* condlin_b = (const float*)d_in[9];
    const float* pre_w     = (const float*)d_in[10];
    const float* pre_b     = (const float*)d_in[11];
    const float* mean_w    = (const float*)d_in[12];
    const float* mean_b    = (const float*)d_in[13];
    const float* std_w     = (const float*)d_in[14];
    const float* std_b     = (const float*)d_in[15];
    const float* eps       = (const float*)d_in[16];
    float* out = (float*)d_out;

    static bool attrSet = false;
    if (!attrSet) {
        cudaFuncSetAttribute(k_layer_mma, cudaFuncAttributeMaxDynamicSharedMemorySize, SMEM_DYN);
        attrSet = true;
    }

    k_prep0<<<189, 256>>>(signal, out, mgc, cond_w, cond_b);
    k_prep1<<<1800 + 12288, 256>>>(condlin_w, condlin_b, convL_w, convL_b);

    for (int blk = 0; blk < 4; blk++) {
        k_layer0<<<51200, 256>>>(conv0_w + blk * 768, conv0_b + blk * 384, blk);
        for (int l = 1; l <= 8; l++) {
            int logL = 8 - l;
            int M = 800 << logL;
            int tiles = (M + BMx - 1) / BMx;
            k_layer_mma<<<dim3(2, tiles), 256, SMEM_DYN>>>(
                (l & 1) ? 0 : 1, blk * 8 + l - 1, blk * 9 + l, M, logL);
        }
        k_head<<<800, 256>>>(pre_w + blk * 256 * 128, pre_b + blk * 256,
                             mean_w + blk * 256, mean_b + blk,
                             std_w + blk * 256, std_b + blk,
                             eps + blk * 800, out, blk);
    }
}

// round 8
// speedup vs baseline: 2.9080x; 1.1403x over previous
#include <cuda_runtime.h>
#include <cuda_fp16.h>
#include <math.h>
#include <stdint.h>

#define SQC 0.70710678118f

// ---------------- device scratch ----------------
__device__ float g_prev[1312];
__device__ float g_cond[48000];
__device__ float g_ciAll[4 * 9 * 2 * 800 * 128];
__device__ float g_bp[4 * 8 * 384];
__device__ __half g_WpH[4 * 8 * 384 * 256];
__device__ __half g_WpL[4 * 8 * 384 * 256];
__device__ __half g_hA[800 * 256 * 128];
__device__ __half g_hB[800 * 256 * 128];

// ---------------- helpers ----------------
__device__ __forceinline__ uint32_t smem_u32(const void* p) {
    uint32_t a;
    asm("{ .reg .u64 t; cvta.to.shared.u64 t, %1; cvt.u32.u64 %0, t; }" : "=r"(a) : "l"(p));
    return a;
}
__device__ __forceinline__ void cpa16(uint32_t dst, const void* src) {
    asm volatile("cp.async.cg.shared.global [%0], [%1], 16;"
                 :: "r"(dst), "l"((unsigned long long)__cvta_generic_to_global(src)));
}
__device__ __forceinline__ void mma_f16(float* c, const uint32_t* a, const uint32_t* b) {
    asm volatile("mma.sync.aligned.m16n8k16.row.col.f32.f16.f16.f32 "
                 "{%0,%1,%2,%3}, {%4,%5,%6,%7}, {%8,%9}, {%0,%1,%2,%3};"
                 : "+f"(c[0]), "+f"(c[1]), "+f"(c[2]), "+f"(c[3])
                 : "r"(a[0]), "r"(a[1]), "r"(a[2]), "r"(a[3]), "r"(b[0]), "r"(b[1]));
}
#define LDM4(r0, r1, r2, r3, addr) \
    asm volatile("ldmatrix.sync.aligned.m8n8.x4.shared.b16 {%0,%1,%2,%3}, [%4];" \
                 : "=r"(r0), "=r"(r1), "=r"(r2), "=r"(r3) : "r"(addr))
#define LDM2(r0, r1, addr) \
    asm volatile("ldmatrix.sync.aligned.m8n8.x2.shared.b16 {%0,%1}, [%2];" \
                 : "=r"(r0), "=r"(r1) : "r"(addr))

__device__ __forceinline__ float fsig(float x) { return __fdividef(1.f, 1.f + __expf(-x)); }
__device__ __forceinline__ float fth(float x)  { return 2.f * fsig(2.f * x) - 1.f; }

// ---------------- prep 0: init + cond ----------------
__global__ void k_prep0(const float* __restrict__ sig, float* __restrict__ out,
                        const float* __restrict__ mgc, const float* __restrict__ cw,
                        const float* __restrict__ cb) {
    int b = blockIdx.x, tid = threadIdx.x;
    if (b == 188) {
        for (int i = tid; i < 1312; i += 256) g_prev[i] = sig[i];
        for (int i = tid; i < 800; i += 256) out[i] = sig[512 + i];
        return;
    }
    int id = b * 256 + tid;
    if (id >= 48000) return;
    int t = id / 12000, w = id % 12000;
    const float* wr = cw + w * 60;
    const float* mg = mgc + t * 60;
    float s = cb[w];
#pragma unroll
    for (int k = 0; k < 60; k++) s += mg[k] * wr[k];
    g_cond[(t * 200 + w / 60) * 60 + (w % 60)] = tanhf(s);
}

// ---------------- prep 1: ciall + wprep (fused) ----------------
__global__ void k_prep1(const float* __restrict__ clw, const float* __restrict__ clb,
                        const float* __restrict__ wL, const float* __restrict__ bL) {
    int b = blockIdx.x, tid = threadIdx.x;
    if (b < 1800) {
        __shared__ float cs[32][60];
        int wg = b / 25, nt = b % 25;
        for (int i = tid; i < 32 * 60; i += 256)
            cs[i / 60][i % 60] = g_cond[(nt * 32 + i / 60) * 60 + (i % 60)];
        __syncthreads();
        int f = tid & 127, nh = tid >> 7;
        float wr[60];
        const float* wsrc = clw + (wg * 128 + f) * 60;
#pragma unroll
        for (int k = 0; k < 60; k++) wr[k] = wsrc[k];
        float bia = clb[wg * 128 + f];
        for (int nn = nh * 16; nn < nh * 16 + 16; nn++) {
            float s = bia;
#pragma unroll
            for (int k = 0; k < 60; k++) s += wr[k] * cs[nn][k];
            g_ciAll[(wg * 800 + nt * 32 + nn) * 128 + f] = s;
        }
        return;
    }
    int idx = (b - 1800) * 256 + tid;
    const int total = 4 * 8 * 384 * 256;
    if (idx < total) {
        int k  = idx & 255;
        int r  = (idx >> 8) % 384;
        int bl = idx / (384 * 256);
        int f = r / 3, t = r % 3, kk = k >> 7, c = k & 127;
        float w = wL[(((bl * 3 + t) * 128 + f) * 128 + c) * 2 + kk];
        __half hi = __float2half_rn(w);
        g_WpH[idx] = hi;
        g_WpL[idx] = __float2half_rn(w - __half2float(hi));
    }
    if (idx < 4 * 8 * 384) {
        int r = idx % 384, bl = idx / 384;
        g_bp[idx] = bL[(bl * 3 + (r % 3)) * 128 + (r / 3)];
    }
}

// ---------------- layer 0 (Cin=1), half2 stores ----------------
__global__ void k_layer0(const float* __restrict__ w0, const float* __restrict__ b0, int blk) {
    int gid = blockIdx.x * 256 + threadIdx.x;     // pairs: 800*256*64
    if (gid >= 800 * 256 * 64) return;
    int m = gid >> 6, f2 = gid & 63;
    int n = m >> 8, j = m & 255;
    const float* ci = g_ciAll + (size_t)(blk * 9 * 2) * 102400;
    const float* cg = ci + 102400;
    float a = g_prev[n + 2 * j], b = g_prev[n + 2 * j + 1];
    float x2[2];
#pragma unroll
    for (int p = 0; p < 2; p++) {
        int f = f2 * 2 + p;
        float o0 = a * w0[f * 2]         + b * w0[f * 2 + 1]         + b0[f];
        float o1 = a * w0[(128 + f) * 2] + b * w0[(128 + f) * 2 + 1] + b0[128 + f];
        float o2 = a * w0[(256 + f) * 2] + b * w0[(256 + f) * 2 + 1] + b0[256 + f];
        float it = fth(o0 + ci[n * 128 + f]);
        float gt = fsig(o1 + cg[n * 128 + f]);
        x2[p] = (it * gt + o2) * SQC;
    }
    *((__half2*)g_hA + gid) = __floats2half2_rn(x2[0], x2[1]);
}

// ------------- layers 1..8: mma.sync fp16 2-term GEMM + fused gating -------------
// Big:  MI=2, NI=6 -> CTA 64 x 192, 2 CTAs/SM, 3-stage cp.async pipeline.
// Tail: MI=1, NI=3 -> CTA 32 x 96, 3 CTAs/SM, more CTAs for small M.
// NOTE: BH/BL are the GLOBAL weight bases; r0 is the GLOBAL row offset
// (wtile*384 + ntile*BN). Do not pre-offset the pointers.
template<int MI, int NI>
__device__ __forceinline__ void load_tile_t(
    uint32_t base, const __half* A, const __half* BH, const __half* BL,
    int m0, long r0, int k0, int tid)
{
    constexpr int BM = 32 * MI;
    constexpr int BN = 32 * NI;
    constexpr int TOT = (BM + 2 * BN) * 4;
#pragma unroll
    for (int it = 0; it < (TOT + 255) / 256; it++) {
        int c = tid + it * 256;
        if ((TOT % 256 == 0) || c < TOT) {
            if (c < BM * 4) {
                int row = c >> 2, seg = c & 3;
                cpa16(base + row * 80 + seg * 16,
                      A + (size_t)(m0 + row) * 256 + k0 + seg * 8);
            } else {
                int j = c - BM * 4;
                int row = j >> 2, seg = j & 3;
                const __half* src = (row < BN)
                    ? BH + (r0 + row) * 256 + k0 + seg * 8
                    : BL + (r0 + row - BN) * 256 + k0 + seg * 8;
                cpa16(base + BM * 80 + row * 80 + seg * 16, src);
            }
        }
    }
    asm volatile("cp.async.commit_group;");
}

template<int MI, int NI>
__global__ void __launch_bounds__(256, (MI == 2 ? 2 : 3))
k_layer_mma(int dir, int wtile, int lidx, int M, int logL) {
    constexpr int BM = 32 * MI;
    constexpr int BN = 32 * NI;
    constexpr int STAGE = (BM + 2 * BN) * 80;
    constexpr int TRI = BN / 3;
    constexpr int CPITCH = BN + 8;

    extern __shared__ __align__(16) char sm[];
    float* Cs = (float*)sm;
    uint32_t smb = smem_u32(sm);

    const int tid  = threadIdx.x;
    const int lane = tid & 31, wid = tid >> 5;
    const int gid  = lane >> 2, tig = lane & 3;
    const int warpM = wid & 1, warpN = wid >> 1;

    const int ntile = blockIdx.x;              // 0 .. 384/BN-1
    const int m0 = blockIdx.y * BM;
    const long r0 = (long)wtile * 384 + ntile * BN;   // GLOBAL row offset

    const __half* A = dir ? g_hB : g_hA;
    __half* O       = dir ? g_hA : g_hB;

    float acc[MI][NI][4];
#pragma unroll
    for (int a = 0; a < MI; a++)
#pragma unroll
        for (int b = 0; b < NI; b++)
#pragma unroll
            for (int c = 0; c < 4; c++) acc[a][b][c] = 0.f;

    // prologue: stages 0,1
    load_tile_t<MI, NI>(smb, A, g_WpH, g_WpL, m0, r0, 0, tid);
    load_tile_t<MI, NI>(smb + STAGE, A, g_WpH, g_WpL, m0, r0, 32, tid);

    const int aRow = warpM * (16 * MI) + (lane & 15);
    const int aByt = (lane >> 4) * 16;
    const int bRow = warpN * (8 * NI) + ((lane >> 4) << 3) + (lane & 7);
    const int bByt = ((lane >> 3) & 1) * 16;
    // x2 remainder load: lanes 0-15 provide addresses (others ignored/aliased)
    const int bRow2 = warpN * (8 * NI) + (NI / 2) * 16 + (lane & 7);
    const int bByt2 = ((lane >> 3) & 1) * 16;

    for (int ks = 0; ks < 8; ks++) {
        int buf = ks % 3;
        if (ks < 7) asm volatile("cp.async.wait_group 1;");
        else        asm volatile("cp.async.wait_group 0;");
        __syncthreads();
        if (ks < 6)
            load_tile_t<MI, NI>(smb + ((ks + 2) % 3) * STAGE, A, g_WpH, g_WpL,
                                m0, r0, (ks + 2) * 32, tid);

        uint32_t aBase = smb + buf * STAGE + aRow * 80 + aByt;
        uint32_t bBase = smb + buf * STAGE + BM * 80 + bRow * 80 + bByt;
        uint32_t bBase2 = smb + buf * STAGE + BM * 80 + bRow2 * 80 + bByt2;
#pragma unroll
        for (int kf = 0; kf < 2; kf++) {
            uint32_t bf[2][NI][2];
#pragma unroll
            for (int prec = 0; prec < 2; prec++) {
#pragma unroll
                for (int p2 = 0; p2 < NI / 2; p2++) {
                    uint32_t ad = bBase + prec * (BN * 80) + p2 * 16 * 80 + kf * 32;
                    LDM4(bf[prec][2 * p2][0], bf[prec][2 * p2][1],
                         bf[prec][2 * p2 + 1][0], bf[prec][2 * p2 + 1][1], ad);
                }
                if (NI & 1) {
                    uint32_t ad = bBase2 + prec * (BN * 80) + kf * 32;
                    LDM2(bf[prec][NI - 1][0], bf[prec][NI - 1][1], ad);
                }
            }
#pragma unroll
            for (int mi = 0; mi < MI; mi++) {
                uint32_t af[4];
                LDM4(af[0], af[1], af[2], af[3], aBase + mi * 16 * 80 + kf * 32);
#pragma unroll
                for (int ni = 0; ni < NI; ni++) {
                    mma_f16(acc[mi][ni], af, bf[0][ni]);
                    mma_f16(acc[mi][ni], af, bf[1][ni]);
                }
            }
        }
    }
    __syncthreads();

    // ---- epilogue: accums -> smem -> fused gating -> fp16 out ----
#pragma unroll
    for (int mi = 0; mi < MI; mi++)
#pragma unroll
        for (int ni = 0; ni < NI; ni++) {
            int ml = warpM * (16 * MI) + mi * 16 + gid;
            int rl = warpN * (8 * NI) + ni * 8 + tig * 2;
            Cs[ml * CPITCH + rl]           = acc[mi][ni][0];
            Cs[ml * CPITCH + rl + 1]       = acc[mi][ni][1];
            Cs[(ml + 8) * CPITCH + rl]     = acc[mi][ni][2];
            Cs[(ml + 8) * CPITCH + rl + 1] = acc[mi][ni][3];
        }
    __syncthreads();

    constexpr int RPB = 256 / TRI;
    const int fl = tid % TRI;
    const int fg = ntile * TRI + fl;
    const float* bpp = g_bp + wtile * 384 + ntile * BN;
    float b0 = bpp[fl * 3], b1 = bpp[fl * 3 + 1], b2 = bpp[fl * 3 + 2];
    const float* ci = g_ciAll + (size_t)lidx * 2 * 102400;
    const float* cg = ci + 102400;
#pragma unroll
    for (int i = 0; i < BM / RPB; i++) {
        int ml = (tid / TRI) + i * RPB;
        int m = m0 + ml;
        if (m < M) {
            int n = m >> logL;
            float o0 = Cs[ml * CPITCH + fl * 3]     + b0 + ci[(size_t)n * 128 + fg];
            float o1 = Cs[ml * CPITCH + fl * 3 + 1] + b1 + cg[(size_t)n * 128 + fg];
            float o2 = Cs[ml * CPITCH + fl * 3 + 2] + b2;
            float x = (fth(o0) * fsig(o1) + o2) * SQC;
            O[(size_t)m * 128 + fg] = __float2half_rn(x);
        }
    }
}

// ---------------- heads ----------------
__global__ void k_head(const float* __restrict__ pw, const float* __restrict__ pb,
                       const float* __restrict__ mw, const float* __restrict__ mb,
                       const float* __restrict__ sw, const float* __restrict__ sb,
                       const float* __restrict__ eps, float* __restrict__ out, int blk) {
    __shared__ float sm_[256], ss_[256];
    int n = blockIdx.x, o = threadIdx.x;
    const __half* h = g_hA + n * 128;
    const float* w = pw + o * 128;
    float s = pb[o];
#pragma unroll
    for (int k = 0; k < 128; k++) s += __half2float(h[k]) * w[k];
    s = fmaxf(s, 0.f);
    sm_[o] = s * mw[o];
    ss_[o] = s * sw[o];
    __syncthreads();
    for (int st = 128; st > 0; st >>= 1) {
        if (o < st) { sm_[o] += sm_[o + st]; ss_[o] += ss_[o + st]; }
        __syncthreads();
    }
    if (o == 0) {
        float mean = sm_[0] + mb[0];
        float logv = ss_[0] + sb[0];
        float nx = eps[n] * expf(0.5f * logv) + mean;
        out[800 + n]  = mean;
        out[1600 + n] = logv;
        if (n >= 288) out[2400 + blk * 512 + (n - 288)] = nx;
        g_prev[512 + n] = nx;
    }
}

// ---------------- launcher ----------------
extern "C" void kernel_launch(void* const* d_in, const int* in_sizes, int n_in,
                              void* d_out, int out_size) {
    const float* mgc       = (const float*)d_in[0];
    const float* signal    = (const float*)d_in[1];
    const float* cond_w    = (const float*)d_in[2];
    const float* cond_b    = (const float*)d_in[3];
    const float* conv0_w   = (const float*)d_in[4];
    const float* conv0_b   = (const float*)d_in[5];
    const float* convL_w   = (const float*)d_in[6];
    const float* convL_b   = (const float*)d_in[7];
    const float* condlin_w = (const float*)d_in[8];
    const float* condlin_b = (const float*)d_in[9];
    const float* pre_w     = (const float*)d_in[10];
    const float* pre_b     = (const float*)d_in[11];
    const float* mean_w    = (const float*)d_in[12];
    const float* mean_b    = (const float*)d_in[13];
    const float* std_w     = (const float*)d_in[14];
    const float* std_b     = (const float*)d_in[15];
    const float* eps       = (const float*)d_in[16];
    float* out = (float*)d_out;

    const int SMEM_BIG  = (64 + 384) * 80 * 3;   // 107520
    const int SMEM_TAIL = (32 + 192) * 80 * 3;   // 53760

    static bool attrSet = false;
    if (!attrSet) {
        cudaFuncSetAttribute(k_layer_mma<2, 6>, cudaFuncAttributeMaxDynamicSharedMemorySize, SMEM_BIG);
        cudaFuncSetAttribute(k_layer_mma<1, 3>, cudaFuncAttributeMaxDynamicSharedMemorySize, SMEM_TAIL);
        attrSet = true;
    }

    k_prep0<<<189, 256>>>(signal, out, mgc, cond_w, cond_b);
    k_prep1<<<1800 + 12288, 256>>>(condlin_w, condlin_b, convL_w, convL_b);

    for (int blk = 0; blk < 4; blk++) {
        k_layer0<<<51200, 256>>>(conv0_w + blk * 768, conv0_b + blk * 384, blk);
        for (int l = 1; l <= 8; l++) {
            int logL = 8 - l;
            int M = 800 << logL;
            int dir = (l & 1) ? 0 : 1;
            int wt = blk * 8 + l - 1, li = blk * 9 + l;
            if (M > 3200) {
                int tiles = (M + 63) / 64;
                k_layer_mma<2, 6><<<dim3(2, tiles), 256, SMEM_BIG>>>(dir, wt, li, M, logL);
            } else {
                int tiles = (M + 31) / 32;
                k_layer_mma<1, 3><<<dim3(4, tiles), 256, SMEM_TAIL>>>(dir, wt, li, M, logL);
            }
        }
        k_head<<<800, 256>>>(pre_w + blk * 256 * 128, pre_b + blk * 256,
                             mean_w + blk * 256, mean_b + blk,
                             std_w + blk * 256, std_b + blk,
                             eps + blk * 800, out, blk);
    }
}